// round 10
// baseline (speedup 1.0000x reference)
#include <cuda_runtime.h>
#include <cuda_fp16.h>
#include <math.h>

#define Bb 64
#define Tt 1024
#define Ii 64
#define Hh 512
#define G3 1536
#define BT (Bb*Tt)
#define NBLK 128
#define BH (Bb*Hh)

// SMEM byte offsets for the persistent kernel
#define OFF_HI   0                       // h_hi plane [64][520] halves
#define OFF_LO   66560                   // h_lo plane [64][520] halves
#define OFF_WF   133120                  // w fragments: 4096 uint2 = 32 KB
#define OFF_PART 165888                  // 64*12 f32 = 3 KB
#define OFF_OWN  168960                  // 64*4 f32 exact h
#define SMEM_TOTAL_B 169984

// ---------------- scratch (static device allocations only) ----------------
__device__ float g_xg[(size_t)BT * G3];
__device__ float g_y[(size_t)BT * Hh];
__device__ __align__(128) __half g_hhi[2 * BH];   // fp16 hi plane, ping-pong [b][hidden]
__device__ __align__(128) __half g_hlo[2 * BH];   // fp16 lo plane
__device__ float g_wih0T[Ii * G3];
__device__ float g_wih1T[Hh * G3];
__device__ float g_fcwT[Hh * Ii];
__device__ unsigned int g_arrive;
__device__ unsigned int g_gen;

// ---------------- transpose: in[R][C] -> out[C][R] ----------------
__global__ void transpose_k(const float* __restrict__ in, float* __restrict__ out,
                            int R, int C) {
    __shared__ float tile[32][33];
    int c0 = blockIdx.x * 32, r0 = blockIdx.y * 32;
    int x = threadIdx.x, y = threadIdx.y;
#pragma unroll
    for (int j = 0; j < 32; j += 8)
        tile[y + j][x] = in[(size_t)(r0 + y + j) * C + c0 + x];
    __syncthreads();
#pragma unroll
    for (int j = 0; j < 32; j += 8)
        out[(size_t)(c0 + y + j) * R + r0 + x] = tile[x][y + j];
}

// ---------------- tiled GEMM: out[M][N] = X[M][K] @ Wt[K][N] + bias ----------------
__global__ void gemm_bias(const float* __restrict__ X, const float* __restrict__ Wt,
                          const float* __restrict__ bias, float* __restrict__ out,
                          int M, int K, int N) {
    __shared__ float As[16][64];
    __shared__ float Bs[16][64];
    int tid = threadIdx.x;
    int n0 = blockIdx.x * 64, m0 = blockIdx.y * 64;
    int tx = tid % 16, ty = tid / 16;
    int am = tid / 4, ak = (tid % 4) * 4;
    int bk = tid / 16, bn = (tid % 16) * 4;
    float acc[4][4];
#pragma unroll
    for (int i = 0; i < 4; i++)
#pragma unroll
        for (int j = 0; j < 4; j++) acc[i][j] = 0.f;

    for (int k0 = 0; k0 < K; k0 += 16) {
        float4 av = *(const float4*)&X[(size_t)(m0 + am) * K + k0 + ak];
        As[ak + 0][am] = av.x; As[ak + 1][am] = av.y;
        As[ak + 2][am] = av.z; As[ak + 3][am] = av.w;
        *(float4*)&Bs[bk][bn] = *(const float4*)&Wt[(size_t)(k0 + bk) * N + n0 + bn];
        __syncthreads();
#pragma unroll
        for (int k = 0; k < 16; k++) {
            float4 a = *(const float4*)&As[k][ty * 4];
            float4 b = *(const float4*)&Bs[k][tx * 4];
            acc[0][0] += a.x * b.x; acc[0][1] += a.x * b.y; acc[0][2] += a.x * b.z; acc[0][3] += a.x * b.w;
            acc[1][0] += a.y * b.x; acc[1][1] += a.y * b.y; acc[1][2] += a.y * b.z; acc[1][3] += a.y * b.w;
            acc[2][0] += a.z * b.x; acc[2][1] += a.z * b.y; acc[2][2] += a.z * b.z; acc[2][3] += a.z * b.w;
            acc[3][0] += a.w * b.x; acc[3][1] += a.w * b.y; acc[3][2] += a.w * b.z; acc[3][3] += a.w * b.w;
        }
        __syncthreads();
    }
    float4 bv = *(const float4*)&bias[n0 + tx * 4];
#pragma unroll
    for (int i = 0; i < 4; i++) {
        float4 o;
        o.x = acc[i][0] + bv.x; o.y = acc[i][1] + bv.y;
        o.z = acc[i][2] + bv.z; o.w = acc[i][3] + bv.w;
        *(float4*)&out[(size_t)(m0 + ty * 4 + i) * N + n0 + tx * 4] = o;
    }
}

// ---------------- grid barrier ----------------
__global__ void bar_reset() { g_arrive = 0u; g_gen = 0u; }

__device__ __forceinline__ void grid_barrier(unsigned int target) {
    __syncthreads();
    if (threadIdx.x == 0) {
        __threadfence();
        unsigned int a = atomicAdd(&g_arrive, 1u);
        if (a == NBLK - 1) {
            g_arrive = 0u;
            __threadfence();
            atomicExch(&g_gen, target);
        } else {
            while (*((volatile unsigned int*)&g_gen) < target) {}
            __threadfence();
        }
    }
    __syncthreads();
}

// ---------------- mma / async-copy helpers ----------------
__device__ __forceinline__ void mma16816(float* c, unsigned a0, unsigned a1,
                                         unsigned a2, unsigned a3,
                                         unsigned b0, unsigned b1) {
    asm volatile(
        "mma.sync.aligned.m16n8k16.row.col.f32.f16.f16.f32 "
        "{%0,%1,%2,%3}, {%4,%5,%6,%7}, {%8,%9}, {%0,%1,%2,%3};"
        : "+f"(c[0]), "+f"(c[1]), "+f"(c[2]), "+f"(c[3])
        : "r"(a0), "r"(a1), "r"(a2), "r"(a3), "r"(b0), "r"(b1));
}

__device__ __forceinline__ void ldsm4(unsigned& r0, unsigned& r1, unsigned& r2,
                                      unsigned& r3, unsigned addr) {
    asm volatile("ldmatrix.sync.aligned.m8n8.x4.shared.b16 {%0,%1,%2,%3}, [%4];"
                 : "=r"(r0), "=r"(r1), "=r"(r2), "=r"(r3) : "r"(addr));
}

__device__ __forceinline__ unsigned pack2h(__half a, __half b) {
    return (unsigned)__half_as_ushort(a) | ((unsigned)__half_as_ushort(b) << 16);
}

__device__ __forceinline__ void cpa16(unsigned dst, const void* src) {
    asm volatile("cp.async.cg.shared.global [%0], [%1], 16;" :: "r"(dst), "l"(src));
}
__device__ __forceinline__ void cpa_commit() {
    asm volatile("cp.async.commit_group;" ::: "memory");
}

// stage one k-chunk (64 halves of K) of both h planes into padded SMEM rows
__device__ __forceinline__ void stage_chunk(unsigned smem_b, const __half* shi,
                                            const __half* slo, int c, int tid) {
#pragma unroll
    for (int u = 0; u < 2; u++) {
        int q = tid + u * 256;          // 0..511
        int m = q >> 3, seg = q & 7;    // 64 rows x 8 segs of 16B
        unsigned doff = (unsigned)(m * 1040 + c * 128 + seg * 16);
        const __half* s1 = shi + m * 512 + c * 64 + seg * 8;
        const __half* s2 = slo + m * 512 + c * 64 + seg * 8;
        cpa16(smem_b + OFF_HI + doff, s1);
        cpa16(smem_b + OFF_LO + doff, s2);
    }
}

// ---------------- persistent split-fp16 tensor-core GRU layer ----------------
// 128 blocks x 256 threads (8 warps). Block bid owns h-cols j0..j0+3.
__global__ void __launch_bounds__(256, 1)
gru_layer_mma(const float* __restrict__ xg, const float* __restrict__ whh,
              const float* __restrict__ bhh, __half* __restrict__ hhi,
              __half* __restrict__ hlo, float* __restrict__ y) {
    extern __shared__ unsigned char smraw[];
    float* part = (float*)(smraw + OFF_PART);
    float* own  = (float*)(smraw + OFF_OWN);
    uint2* wf   = (uint2*)(smraw + OFF_WF);
    const unsigned smem_b = (unsigned)__cvta_generic_to_shared(smraw);

    const int tid = threadIdx.x, bid = blockIdx.x;
    const int j0 = bid * 4;
    const int lane = tid & 31, wid = tid >> 5;
    const int mi = wid >> 1, ni = wid & 1;

    // ---- one-time: W_hh fragments (hi/lo fp16, mma B-frag order) ----
    for (int q = tid; q < 4096; q += 256) {
        int l = q & 31, ps = (q >> 5) & 1, s = (q >> 6) & 31, nn = q >> 11;
        int c = nn * 8 + (l >> 2), t = l & 3;
        float e0 = 0.f, e1 = 0.f, e2 = 0.f, e3 = 0.f;
        if (c < 12) {
            int g = c >> 2, jj = c & 3;
            const float* wr = whh + (size_t)(g * Hh + j0 + jj) * Hh;
            int k = s * 16 + t * 2;
            e0 = wr[k]; e1 = wr[k + 1]; e2 = wr[k + 8]; e3 = wr[k + 9];
        }
        __half h0 = __float2half_rn(e0), h1 = __float2half_rn(e1);
        __half h2v = __float2half_rn(e2), h3 = __float2half_rn(e3);
        if (ps) {
            h0 = __float2half_rn(e0 - __half2float(h0));
            h1 = __float2half_rn(e1 - __half2float(h1));
            h2v = __float2half_rn(e2 - __half2float(h2v));
            h3 = __float2half_rn(e3 - __half2float(h3));
        }
        uint2 v; v.x = pack2h(h0, h1); v.y = pack2h(h2v, h3);
        wf[q] = v;
    }

    // zero h planes (slot 0) + own exact-h
    {
        int i = bid * 256 + tid;   // exactly BH threads chip-wide
        hhi[i] = __float2half_rn(0.f);
        hlo[i] = __float2half_rn(0.f);
    }
    own[tid] = 0.f;

    // hoisted per-thread constants for the update phase
    const int ub = tid >> 2, uj = tid & 3;
    const float bhr = bhh[j0 + uj];
    const float bhz = bhh[Hh + j0 + uj];
    const float bhn = bhh[2 * Hh + j0 + uj];
    const float* xp = xg + (size_t)ub * Tt * G3 + j0 + uj;
    float* yp = y + (size_t)ub * Tt * Hh + j0 + uj;

    // ldmatrix addresses (A tiles)
    const unsigned aoff = (unsigned)(((mi * 16 + (lane & 15)) * 520 + ((lane >> 4) * 8)) * 2);
    const unsigned a_hi = smem_b + OFF_HI + aoff;
    const unsigned a_lo = smem_b + OFF_LO + aoff;
    const unsigned bbase = smem_b + OFF_WF + (unsigned)(ni * 16384 + lane * 8);

    unsigned int bar = 0;
    grid_barrier(++bar);

    for (int t = 0; t < Tt; t++) {
        const __half* shi = hhi + (t & 1) * BH;
        const __half* slo = hlo + (t & 1) * BH;
        __half* nhi = hhi + ((t + 1) & 1) * BH;
        __half* nlo = hlo + ((t + 1) & 1) * BH;

        // prefetch xg (DRAM) for the gate phase
        float xr = xp[(size_t)t * G3];
        float xz = xp[(size_t)t * G3 + Hh];
        float xn = xp[(size_t)t * G3 + 2 * Hh];

        // ---- pipelined stage + mma over 8 k-chunks (64 halves each) ----
        float chh[4] = {0.f, 0.f, 0.f, 0.f};
        float chl[4] = {0.f, 0.f, 0.f, 0.f};
        float clh[4] = {0.f, 0.f, 0.f, 0.f};

        stage_chunk(smem_b, shi, slo, 0, tid);
        cpa_commit();

#pragma unroll
        for (int c = 0; c < 8; c++) {
            if (c < 7) {
                stage_chunk(smem_b, shi, slo, c + 1, tid);
                cpa_commit();
                asm volatile("cp.async.wait_group 1;" ::: "memory");
            } else {
                asm volatile("cp.async.wait_group 0;" ::: "memory");
            }
            __syncthreads();
#pragma unroll
            for (int s = c * 4; s < c * 4 + 4; s++) {
                unsigned Ah0, Ah1, Ah2, Ah3, Al0, Al1, Al2, Al3;
                ldsm4(Ah0, Ah1, Ah2, Ah3, a_hi + s * 32);
                ldsm4(Al0, Al1, Al2, Al3, a_lo + s * 32);
                unsigned bh0, bh1, bl0, bl1;
                asm volatile("ld.shared.v2.u32 {%0,%1}, [%2];"
                             : "=r"(bh0), "=r"(bh1) : "r"(bbase + s * 512));
                asm volatile("ld.shared.v2.u32 {%0,%1}, [%2];"
                             : "=r"(bl0), "=r"(bl1) : "r"(bbase + s * 512 + 256));
                mma16816(chh, Ah0, Ah1, Ah2, Ah3, bh0, bh1);
                mma16816(chl, Ah0, Ah1, Ah2, Ah3, bl0, bl1);
                mma16816(clh, Al0, Al1, Al2, Al3, bh0, bh1);
            }
        }
        {
            float d0 = chh[0] + chl[0] + clh[0];
            float d1 = chh[1] + chl[1] + clh[1];
            float d2 = chh[2] + chl[2] + clh[2];
            float d3 = chh[3] + chl[3] + clh[3];
            int r = lane >> 2, tc = (lane & 3) * 2;
            int b = mi * 16 + r;
            int c0 = ni * 8 + tc;
            if (c0 < 12) { part[b * 12 + c0] = d0; part[(b + 8) * 12 + c0] = d2; }
            if (c0 + 1 < 12) { part[b * 12 + c0 + 1] = d1; part[(b + 8) * 12 + c0 + 1] = d3; }
        }
        __syncthreads();

        // ---- gate update (all 256 threads: (b, j)) ----
        {
            float hr = bhr + part[ub * 12 + uj];
            float hz = bhz + part[ub * 12 + 4 + uj];
            float hn_ = bhn + part[ub * 12 + 8 + uj];
            float r = 1.f / (1.f + expf(-(xr + hr)));
            float z = 1.f / (1.f + expf(-(xz + hz)));
            float n = tanhf(xn + r * hn_);
            float hp = own[ub * 4 + uj];
            float v = (1.f - z) * n + z * hp;
            own[ub * 4 + uj] = v;
            __half vh = __float2half_rn(v);
            __half vl = __float2half_rn(v - __half2float(vh));
            nhi[ub * Hh + j0 + uj] = vh;
            nlo[ub * Hh + j0 + uj] = vl;
            yp[(size_t)t * Hh] = v;
        }
        grid_barrier(++bar);
    }
}

// ---------------- launch ----------------
extern "C" void kernel_launch(void* const* d_in, const int* in_sizes, int n_in,
                              void* d_out, int out_size) {
    const float* x     = (const float*)d_in[0];
    const float* w_ih0 = (const float*)d_in[1];
    const float* w_hh0 = (const float*)d_in[2];
    const float* b_ih0 = (const float*)d_in[3];
    const float* b_hh0 = (const float*)d_in[4];
    const float* w_ih1 = (const float*)d_in[5];
    const float* w_hh1 = (const float*)d_in[6];
    const float* b_ih1 = (const float*)d_in[7];
    const float* b_hh1 = (const float*)d_in[8];
    const float* fc_w  = (const float*)d_in[9];
    const float* fc_b  = (const float*)d_in[10];
    float* out = (float*)d_out;

    float *xg, *y, *wih0T, *wih1T, *fcwT;
    __half *hhi, *hlo;
    cudaGetSymbolAddress((void**)&xg,    g_xg);
    cudaGetSymbolAddress((void**)&y,     g_y);
    cudaGetSymbolAddress((void**)&hhi,   g_hhi);
    cudaGetSymbolAddress((void**)&hlo,   g_hlo);
    cudaGetSymbolAddress((void**)&wih0T, g_wih0T);
    cudaGetSymbolAddress((void**)&wih1T, g_wih1T);
    cudaGetSymbolAddress((void**)&fcwT,  g_fcwT);

    cudaFuncSetAttribute(gru_layer_mma,
                         cudaFuncAttributeMaxDynamicSharedMemorySize, SMEM_TOTAL_B);

    dim3 tb(32, 8);
    transpose_k<<<dim3(Ii / 32, G3 / 32), tb>>>(w_ih0, wih0T, G3, Ii);
    transpose_k<<<dim3(Hh / 32, G3 / 32), tb>>>(w_ih1, wih1T, G3, Hh);
    transpose_k<<<dim3(Hh / 32, Ii / 32), tb>>>(fc_w,  fcwT,  Ii, Hh);

    // -------- layer 0 --------
    gemm_bias<<<dim3(G3 / 64, BT / 64), 256>>>(x, wih0T, b_ih0, xg, BT, Ii, G3);
    bar_reset<<<1, 1>>>();
    gru_layer_mma<<<NBLK, 256, SMEM_TOTAL_B>>>(xg, w_hh0, b_hh0, hhi, hlo, y);

    // -------- layer 1 --------
    gemm_bias<<<dim3(G3 / 64, BT / 64), 256>>>(y, wih1T, b_ih1, xg, BT, Hh, G3);
    bar_reset<<<1, 1>>>();
    gru_layer_mma<<<NBLK, 256, SMEM_TOTAL_B>>>(xg, w_hh1, b_hh1, hhi, hlo, y);

    // -------- final FC --------
    gemm_bias<<<dim3(Ii / 64, BT / 64), 256>>>(y, fcwT, fc_b, out, BT, Hh, Ii);
}